// round 3
// baseline (speedup 1.0000x reference)
#include <cuda_runtime.h>

// ---------------- problem constants (shapes are fixed by the dataset) -------
#define MAXN 100000
#define HC   64
#define MAXG 512
#define EPSV 1e-5f

// ---------------- device scratch (static; no allocation) --------------------
__device__ float g_bufA[MAXN * HC];   // projected features (xW)
__device__ float g_bufB[MAXN * HC];   // aggregated features (h)
__device__ float g_dis[MAXN];         // deg -> rsqrt(deg)
__device__ float g_sum1[HC];
__device__ float g_sq1[HC];
__device__ float g_sum2[HC];
__device__ float g_sq2[HC];
__device__ float g_pool[MAXG * HC];
__device__ float g_cnt[MAXG];
__device__ int   g_is64;

// ---------------- dtype-agnostic index load --------------------------------
__device__ __forceinline__ long long ld_idx(const void* p, long long i) {
    if (g_is64) return ((const long long*)p)[i];
    return (long long)((const int*)p)[i];
}

// Detect whether index buffers are int64 or int32. If the data is really
// int32, reading pairs as int64 yields values >= 2^32 with overwhelming
// probability over 64 samples (hi half is a random node id, ==0 w.p. 1e-5).
__global__ void k_detect(const void* ei, long long n_nodes) {
    const long long* p = (const long long*)ei;
    int ok = 1;
    for (int i = 0; i < 64; i++) {
        long long v = p[i];
        if (v < 0 || v >= n_nodes) { ok = 0; break; }
    }
    g_is64 = ok;
}

// ---------------- init: deg=1 (self loop), zero pool/cnt/bn sums ------------
__global__ void k_init(long long n) {
    long long i = blockIdx.x * (long long)blockDim.x + threadIdx.x;
    if (i < n)          g_dis[i] = 1.0f;
    if (i < MAXG * HC)  g_pool[i] = 0.0f;
    if (i < MAXG)       g_cnt[i] = 0.0f;
    if (i < HC) { g_sum1[i] = 0.f; g_sq1[i] = 0.f; g_sum2[i] = 0.f; g_sq2[i] = 0.f; }
}

__global__ void k_deg(const void* ei, long long E) {
    long long e = blockIdx.x * (long long)blockDim.x + threadIdx.x;
    if (e >= E) return;
    long long d = ld_idx(ei, E + e);
    atomicAdd(&g_dis[d], 1.0f);
}

__global__ void k_rsqrt(long long n) {
    long long i = blockIdx.x * (long long)blockDim.x + threadIdx.x;
    if (i < n) g_dis[i] = rsqrtf(g_dis[i]);
}

// ---------------- GEMM: C[N,64] = A[N,K] @ W[K,64] --------------------------
// 128 threads, block tile 32 rows x 64 cols, 4x4 register tile per thread.
template <int K>
__global__ void k_gemm(const float* __restrict__ A, const float* __restrict__ W,
                       float* __restrict__ C, long long n) {
    __shared__ float xsT[32][36];   // transposed x tile, 36 keeps rows 16B-aligned
    __shared__ float ws[32][64];
    const int tid = threadIdx.x;
    const int tx = tid & 15;        // column group (4 cols)
    const int ty = tid >> 4;        // row group    (4 rows)
    const long long row0 = (long long)blockIdx.x * 32;
    float acc[4][4] = {};

    for (int k0 = 0; k0 < K; k0 += 32) {
        // load 32x32 x-tile, transposed into xsT
        {
            int r  = tid >> 2;          // 0..31
            int kk = (tid & 3) * 8;     // 0,8,16,24
            long long row = row0 + r;
            float4 v0 = make_float4(0.f, 0.f, 0.f, 0.f), v1 = v0;
            if (row < n) {
                const float* src = A + row * (long long)K + k0 + kk;
                v0 = *(const float4*)src;
                v1 = *(const float4*)(src + 4);
            }
            xsT[kk + 0][r] = v0.x; xsT[kk + 1][r] = v0.y;
            xsT[kk + 2][r] = v0.z; xsT[kk + 3][r] = v0.w;
            xsT[kk + 4][r] = v1.x; xsT[kk + 5][r] = v1.y;
            xsT[kk + 6][r] = v1.z; xsT[kk + 7][r] = v1.w;
        }
        // load 32x64 W tile
#pragma unroll
        for (int j = 0; j < 4; j++) {
            int fi = tid + j * 128;          // 0..511 float4 slots
            int kk = fi >> 4;
            int cc = (fi & 15) * 4;
            *(float4*)&ws[kk][cc] = *(const float4*)(W + (long long)(k0 + kk) * 64 + cc);
        }
        __syncthreads();
#pragma unroll
        for (int kk = 0; kk < 32; kk++) {
            float4 a = *(const float4*)&xsT[kk][ty * 4];
            float4 b = *(const float4*)&ws[kk][tx * 4];
            acc[0][0] += a.x * b.x; acc[0][1] += a.x * b.y; acc[0][2] += a.x * b.z; acc[0][3] += a.x * b.w;
            acc[1][0] += a.y * b.x; acc[1][1] += a.y * b.y; acc[1][2] += a.y * b.z; acc[1][3] += a.y * b.w;
            acc[2][0] += a.z * b.x; acc[2][1] += a.z * b.y; acc[2][2] += a.z * b.z; acc[2][3] += a.z * b.w;
            acc[3][0] += a.w * b.x; acc[3][1] += a.w * b.y; acc[3][2] += a.w * b.z; acc[3][3] += a.w * b.w;
        }
        __syncthreads();
    }
#pragma unroll
    for (int i = 0; i < 4; i++) {
        long long row = row0 + ty * 4 + i;
        if (row < n)
            *(float4*)(C + row * 64 + tx * 4) =
                make_float4(acc[i][0], acc[i][1], acc[i][2], acc[i][3]);
    }
}

// ---------------- self loop + bias init: out = b[c] + dis[i]^2 * xw ---------
__global__ void k_selfinit(const float* __restrict__ xw, const float* __restrict__ bias,
                           float* __restrict__ out, long long n64) {
    long long idx = blockIdx.x * (long long)blockDim.x + threadIdx.x;
    if (idx >= n64) return;
    long long i = idx >> 6;
    int c = (int)(idx & 63);
    float d = g_dis[i];
    out[idx] = bias[c] + d * d * xw[idx];
}

// ---------------- edge aggregation: hout[dst] += dis[s]*dis[d]*xw[src] ------
// 16 threads per edge, each owns a float4 channel chunk; red.global.add.v4.f32
__global__ void k_agg(const void* ei, long long E, const float* __restrict__ xw,
                      float* __restrict__ hout) {
    long long t = blockIdx.x * (long long)blockDim.x + threadIdx.x;
    if (t >= E * 16) return;
    long long e = t >> 4;
    int ch = (int)(t & 15) * 4;
    long long s = ld_idx(ei, e);
    long long d = ld_idx(ei, E + e);
    float nn = g_dis[s] * g_dis[d];
    float4 v = *(const float4*)(xw + s * 64 + ch);
    float* dst = hout + d * 64 + ch;
    asm volatile("red.global.add.v4.f32 [%0], {%1,%2,%3,%4};"
                 :: "l"(dst), "f"(v.x * nn), "f"(v.y * nn), "f"(v.z * nn), "f"(v.w * nn)
                 : "memory");
}

// ---------------- relu in-place + per-channel sum / sumsq -------------------
// stride is a multiple of 64, so each thread's channel is fixed.
__global__ void k_relustats(float* __restrict__ buf, float* __restrict__ gsum,
                            float* __restrict__ gsq, long long n64) {
    __shared__ float ss[HC], sq[HC];
    int tid = threadIdx.x;
    if (tid < HC) { ss[tid] = 0.f; sq[tid] = 0.f; }
    __syncthreads();
    long long start  = blockIdx.x * (long long)blockDim.x + tid;
    long long stride = (long long)gridDim.x * blockDim.x;
    int c = (int)(start & 63);
    float s = 0.f, q = 0.f;
    for (long long idx = start; idx < n64; idx += stride) {
        float v = fmaxf(buf[idx], 0.f);
        buf[idx] = v;
        s += v; q += v * v;
    }
    atomicAdd(&ss[c], s);
    atomicAdd(&sq[c], q);
    __syncthreads();
    if (tid < HC) { atomicAdd(&gsum[tid], ss[tid]); atomicAdd(&gsq[tid], sq[tid]); }
}

// ---------------- BN apply (in place) ----------------------------------------
__global__ void k_bn(float* __restrict__ buf, const float* __restrict__ gsum,
                     const float* __restrict__ gsq, const float* __restrict__ gamma,
                     const float* __restrict__ beta, float invN, long long n64) {
    long long idx = blockIdx.x * (long long)blockDim.x + threadIdx.x;
    if (idx >= n64) return;
    int c = (int)(idx & 63);
    float m   = gsum[c] * invN;
    float var = gsq[c] * invN - m * m;
    float sc  = rsqrtf(var + EPSV) * gamma[c];
    buf[idx] = (buf[idx] - m) * sc + beta[c];
}

// ---------------- BN apply + global mean pool accumulation ------------------
__global__ void k_bnpool(const float* __restrict__ buf, const float* __restrict__ gsum,
                         const float* __restrict__ gsq, const float* __restrict__ gamma,
                         const float* __restrict__ beta, const void* batch,
                         float invN, long long n64) {
    long long idx = blockIdx.x * (long long)blockDim.x + threadIdx.x;
    if (idx >= n64) return;
    long long i = idx >> 6;
    int c = (int)(idx & 63);
    float m   = gsum[c] * invN;
    float var = gsq[c] * invN - m * m;
    float sc  = rsqrtf(var + EPSV) * gamma[c];
    float val = (buf[idx] - m) * sc + beta[c];
    long long b = ld_idx(batch, i);
    atomicAdd(&g_pool[b * 64 + c], val);
    if (c == 0) atomicAdd(&g_cnt[b], 1.0f);
}

// ---------------- fused MLP head: one block per graph -----------------------
__global__ void k_mlp(const float* __restrict__ fw1, const float* __restrict__ fb1,
                      const float* __restrict__ fw2, const float* __restrict__ fb2,
                      const float* __restrict__ fw3, const float* __restrict__ fb3,
                      const float* __restrict__ fw4, const float* __restrict__ fb4,
                      const float* __restrict__ ow,  const float* __restrict__ ob,
                      float* __restrict__ out) {
    __shared__ float p[64], a1[128], a2[64], a3[32], a4[16];
    int g = blockIdx.x, t = threadIdx.x;
    float inv = 1.0f / fmaxf(g_cnt[g], 1.0f);
    if (t < 64) p[t] = g_pool[g * 64 + t] * inv;
    __syncthreads();
    if (t < 128) {
        float a = fb1[t];
#pragma unroll 8
        for (int k = 0; k < 64; k++) a += p[k] * fw1[k * 128 + t];
        a1[t] = fmaxf(a, 0.f);
    }
    __syncthreads();
    if (t < 64) {
        float a = fb2[t];
#pragma unroll 8
        for (int k = 0; k < 128; k++) a += a1[k] * fw2[k * 64 + t];
        a2[t] = fmaxf(a, 0.f);
    }
    __syncthreads();
    if (t < 32) {
        float a = fb3[t];
#pragma unroll 8
        for (int k = 0; k < 64; k++) a += a2[k] * fw3[k * 32 + t];
        a3[t] = fmaxf(a, 0.f);
    }
    __syncthreads();
    if (t < 16) {
        float a = fb4[t];
#pragma unroll
        for (int k = 0; k < 32; k++) a += a3[k] * fw4[k * 16 + t];
        a4[t] = fmaxf(a, 0.f);
    }
    __syncthreads();
    if (t < 2) {
        float a = ob[t];
#pragma unroll
        for (int k = 0; k < 16; k++) a += a4[k] * ow[k * 2 + t];
        out[g * 2 + t] = a;
    }
}

// ---------------- launcher ---------------------------------------------------
extern "C" void kernel_launch(void* const* d_in, const int* in_sizes, int n_in,
                              void* d_out, int out_size) {
    const float* x   = (const float*)d_in[0];
    const void*  ei  = d_in[1];
    const void*  bat = d_in[2];
    const float* w1  = (const float*)d_in[3];
    const float* b1  = (const float*)d_in[4];
    const float* w2  = (const float*)d_in[5];
    const float* b2  = (const float*)d_in[6];
    const float* g1  = (const float*)d_in[7];
    const float* be1 = (const float*)d_in[8];
    const float* g2  = (const float*)d_in[9];
    const float* be2 = (const float*)d_in[10];
    const float* fw1 = (const float*)d_in[11];
    const float* fb1 = (const float*)d_in[12];
    const float* fw2 = (const float*)d_in[13];
    const float* fb2 = (const float*)d_in[14];
    const float* fw3 = (const float*)d_in[15];
    const float* fb3 = (const float*)d_in[16];
    const float* fw4 = (const float*)d_in[17];
    const float* fb4 = (const float*)d_in[18];
    const float* ow  = (const float*)d_in[19];
    const float* ob  = (const float*)d_in[20];
    float* out = (float*)d_out;

    const long long N   = in_sizes[0] / 256;   // C = 256
    const long long E   = in_sizes[1] / 2;
    const int       G   = out_size / 2;
    const long long n64 = N * 64;
    const float invN = 1.0f / (float)N;

    float *bufA, *bufB, *sum1, *sq1, *sum2, *sq2;
    cudaGetSymbolAddress((void**)&bufA, g_bufA);
    cudaGetSymbolAddress((void**)&bufB, g_bufB);
    cudaGetSymbolAddress((void**)&sum1, g_sum1);
    cudaGetSymbolAddress((void**)&sq1,  g_sq1);
    cudaGetSymbolAddress((void**)&sum2, g_sum2);
    cudaGetSymbolAddress((void**)&sq2,  g_sq2);

    const int TB = 256;
    const int gN   = (int)((N + TB - 1) / TB);
    const int gE   = (int)((E + TB - 1) / TB);
    const int gN64 = (int)((n64 + TB - 1) / TB);
    const int gAgg = (int)((E * 16 + TB - 1) / TB);
    const int gGemm = (int)((N + 31) / 32);

    k_detect<<<1, 1>>>(ei, N);
    k_init<<<gN, TB>>>(N);
    k_deg<<<gE, TB>>>(ei, E);
    k_rsqrt<<<gN, TB>>>(N);

    // ---- GCN layer 1 ----
    k_gemm<256><<<gGemm, 128>>>(x, w1, bufA, N);
    k_selfinit<<<gN64, TB>>>(bufA, b1, bufB, n64);
    k_agg<<<gAgg, TB>>>(ei, E, bufA, bufB);
    k_relustats<<<2048, TB>>>(bufB, sum1, sq1, n64);
    k_bn<<<gN64, TB>>>(bufB, sum1, sq1, g1, be1, invN, n64);

    // ---- GCN layer 2 ----
    k_gemm<64><<<gGemm, 128>>>(bufB, w2, bufA, N);
    k_selfinit<<<gN64, TB>>>(bufA, b2, bufB, n64);
    k_agg<<<gAgg, TB>>>(ei, E, bufA, bufB);
    k_relustats<<<2048, TB>>>(bufB, sum2, sq2, n64);
    k_bnpool<<<gN64, TB>>>(bufB, sum2, sq2, g2, be2, bat, invN, n64);

    // ---- MLP head ----
    k_mlp<<<G, 128>>>(fw1, fb1, fw2, fb2, fw3, fb3, fw4, fb4, ow, ob, out);
}

// round 4
// speedup vs baseline: 1.5407x; 1.5407x over previous
#include <cuda_runtime.h>

// ---------------- problem constants (shapes fixed by the dataset) -----------
#define MAXN 100000
#define MAXE 3342336
#define HC   64
#define MAXG 512
#define EPSV 1e-5f

// ---------------- device scratch (static; no allocation) --------------------
__device__ float g_bufA[MAXN * HC];      // projected features (xW)
__device__ float g_bufB[MAXN * HC];      // aggregated features (h)
__device__ float g_dis[MAXN];            // rsqrt(deg)
__device__ int   g_deg[MAXN];            // in-degree (w/o self loop)
__device__ int   g_rowptr[MAXN + 1];
__device__ int   g_cursor[MAXN];
__device__ int   g_csr[MAXE];            // src ids grouped by dst
__device__ int   g_bsum[512];
__device__ int   g_boff[512];
__device__ float g_sum1[HC], g_sq1[HC], g_sum2[HC], g_sq2[HC];
__device__ float g_pool[MAXG * HC];
__device__ float g_cnt[MAXG];
__device__ int   g_is64;

// ---------------- dtype-agnostic index load ---------------------------------
__device__ __forceinline__ long long ld_idx(const void* p, long long i) {
    if (g_is64) return ((const long long*)p)[i];
    return (long long)((const int*)p)[i];
}

__global__ void k_detect(const void* ei, long long n_nodes) {
    const long long* p = (const long long*)ei;
    int ok = 1;
    for (int i = 0; i < 64; i++) {
        long long v = p[i];
        if (v < 0 || v >= n_nodes) { ok = 0; break; }
    }
    g_is64 = ok;
}

// ---------------- packed f32x2 helpers (Blackwell) --------------------------
__device__ __forceinline__ unsigned long long dupf(float a) {
    unsigned long long r; unsigned int u = __float_as_uint(a);
    asm("mov.b64 %0, {%1, %1};" : "=l"(r) : "r"(u));
    return r;
}
__device__ __forceinline__ void ffma2(unsigned long long& d,
                                      unsigned long long a, unsigned long long b) {
    asm("fma.rn.f32x2 %0, %1, %2, %0;" : "+l"(d) : "l"(a), "l"(b));
}
__device__ __forceinline__ float2 unpk(unsigned long long v) {
    unsigned int lo, hi;
    asm("mov.b64 {%0, %1}, %2;" : "=r"(lo), "=r"(hi) : "l"(v));
    return make_float2(__uint_as_float(lo), __uint_as_float(hi));
}

// ---------------- init: zero deg/pool/cnt/bn sums ----------------------------
__global__ void k_zero(long long n) {
    long long i = blockIdx.x * (long long)blockDim.x + threadIdx.x;
    if (i < n)          g_deg[i] = 0;
    if (i < MAXG * HC)  g_pool[i] = 0.0f;
    if (i < MAXG)       g_cnt[i] = 0.0f;
    if (i < HC) { g_sum1[i] = 0.f; g_sq1[i] = 0.f; g_sum2[i] = 0.f; g_sq2[i] = 0.f; }
}

__global__ void k_hist(const void* ei, long long E) {
    long long e = blockIdx.x * (long long)blockDim.x + threadIdx.x;
    if (e >= E) return;
    atomicAdd(&g_deg[ld_idx(ei, E + e)], 1);
}

// ---------------- exclusive scan over g_deg ----------------------------------
__global__ void k_scan1(long long n) {
    __shared__ int wsum[8];
    int t = threadIdx.x;
    long long i = blockIdx.x * 256LL + t;
    int v = (i < n) ? g_deg[i] : 0;
    int x = v;
#pragma unroll
    for (int o = 1; o < 32; o <<= 1) {
        int y = __shfl_up_sync(~0u, x, o);
        if ((t & 31) >= o) x += y;
    }
    if ((t & 31) == 31) wsum[t >> 5] = x;
    __syncthreads();
    if (t < 8) {
        int y = wsum[t];
#pragma unroll
        for (int o = 1; o < 8; o <<= 1) {
            int z = __shfl_up_sync(0xff, y, o);
            if (t >= o) y += z;
        }
        wsum[t] = y;
    }
    __syncthreads();
    int base = (t >= 32) ? wsum[(t >> 5) - 1] : 0;
    int incl = x + base;
    if (i < n) g_rowptr[i] = incl - v;               // block-local exclusive
    if (t == 255) g_bsum[blockIdx.x] = incl;          // block total
}

__global__ void k_scan2(int nb) {
    __shared__ int wsum[16];
    int t = threadIdx.x;
    int v = (t < nb) ? g_bsum[t] : 0;
    int x = v;
#pragma unroll
    for (int o = 1; o < 32; o <<= 1) {
        int y = __shfl_up_sync(~0u, x, o);
        if ((t & 31) >= o) x += y;
    }
    if ((t & 31) == 31) wsum[t >> 5] = x;
    __syncthreads();
    if (t < 16) {
        int y = wsum[t];
#pragma unroll
        for (int o = 1; o < 16; o <<= 1) {
            int z = __shfl_up_sync(0xffff, y, o);
            if (t >= o) y += z;
        }
        wsum[t] = y;
    }
    __syncthreads();
    int base = (t >= 32) ? wsum[(t >> 5) - 1] : 0;
    g_boff[t] = x + base - v;                          // exclusive
}

__global__ void k_scan3(long long n, int E) {
    long long i = blockIdx.x * (long long)blockDim.x + threadIdx.x;
    if (i < n) {
        int rp = g_rowptr[i] + g_boff[i >> 8];
        g_rowptr[i] = rp;
        g_cursor[i] = rp;
        g_dis[i] = rsqrtf((float)(g_deg[i] + 1));      // +1 self loop
    }
    if (i == 0) g_rowptr[n] = E;
}

__global__ void k_scatter(const void* ei, long long E) {
    long long e = blockIdx.x * (long long)blockDim.x + threadIdx.x;
    if (e >= E) return;
    long long s = ld_idx(ei, e);
    long long d = ld_idx(ei, E + e);
    int pos = atomicAdd(&g_cursor[d], 1);
    g_csr[pos] = (int)s;
}

// ---------------- GEMM: C[N,64] = A[N,K] @ W[K,64], packed f32x2 ------------
template <int K>
__global__ void k_gemm(const float* __restrict__ A, const float* __restrict__ W,
                       float* __restrict__ C, long long n) {
    __shared__ __align__(16) float xsT[32][36];
    __shared__ __align__(16) float ws[32][64];
    const int tid = threadIdx.x;
    const int tx = tid & 15;        // column group (4 cols = 2 pairs)
    const int ty = tid >> 4;        // row group    (4 rows)
    const long long row0 = (long long)blockIdx.x * 32;
    unsigned long long acc[4][2] = {};

    for (int k0 = 0; k0 < K; k0 += 32) {
        {
            int r  = tid >> 2;
            int kk = (tid & 3) * 8;
            long long row = row0 + r;
            float4 v0 = make_float4(0.f, 0.f, 0.f, 0.f), v1 = v0;
            if (row < n) {
                const float* src = A + row * (long long)K + k0 + kk;
                v0 = *(const float4*)src;
                v1 = *(const float4*)(src + 4);
            }
            xsT[kk + 0][r] = v0.x; xsT[kk + 1][r] = v0.y;
            xsT[kk + 2][r] = v0.z; xsT[kk + 3][r] = v0.w;
            xsT[kk + 4][r] = v1.x; xsT[kk + 5][r] = v1.y;
            xsT[kk + 6][r] = v1.z; xsT[kk + 7][r] = v1.w;
        }
#pragma unroll
        for (int j = 0; j < 4; j++) {
            int fi = tid + j * 128;
            int kk = fi >> 4;
            int cc = (fi & 15) * 4;
            *(float4*)&ws[kk][cc] = *(const float4*)(W + (long long)(k0 + kk) * 64 + cc);
        }
        __syncthreads();
#pragma unroll
        for (int kk = 0; kk < 32; kk++) {
            float4 a = *(const float4*)&xsT[kk][ty * 4];
            const unsigned long long* bp = (const unsigned long long*)&ws[kk][tx * 4];
            unsigned long long b01 = bp[0], b23 = bp[1];
            unsigned long long a0 = dupf(a.x), a1 = dupf(a.y),
                               a2 = dupf(a.z), a3 = dupf(a.w);
            ffma2(acc[0][0], a0, b01); ffma2(acc[0][1], a0, b23);
            ffma2(acc[1][0], a1, b01); ffma2(acc[1][1], a1, b23);
            ffma2(acc[2][0], a2, b01); ffma2(acc[2][1], a2, b23);
            ffma2(acc[3][0], a3, b01); ffma2(acc[3][1], a3, b23);
        }
        __syncthreads();
    }
#pragma unroll
    for (int i = 0; i < 4; i++) {
        long long row = row0 + ty * 4 + i;
        if (row < n) {
            float2 c0 = unpk(acc[i][0]), c1 = unpk(acc[i][1]);
            *(float4*)(C + row * 64 + tx * 4) = make_float4(c0.x, c0.y, c1.x, c1.y);
        }
    }
}

// ---------------- fused CSR gather: self loop + bias + agg + relu + stats ---
// 16 threads per node, each owns a float4 channel chunk.
__global__ void k_gather(const float* __restrict__ xw, const float* __restrict__ bias,
                         float* __restrict__ out, long long n,
                         float* __restrict__ gsum, float* __restrict__ gsq) {
    __shared__ float ss[HC], sq[HC];
    int t = threadIdx.x;
    if (t < HC) { ss[t] = 0.f; sq[t] = 0.f; }
    __syncthreads();
    int grp = t >> 4;
    int ch  = (t & 15) * 4;
    long long node = blockIdx.x * 16LL + grp;
    if (node < n) {
        float dd = g_dis[node];
        float4 bv = *(const float4*)(bias + ch);
        float4 xv = *(const float4*)(xw + node * 64 + ch);
        float w0 = dd * dd;
        float4 acc = make_float4(bv.x + w0 * xv.x, bv.y + w0 * xv.y,
                                 bv.z + w0 * xv.z, bv.w + w0 * xv.w);
        int beg = g_rowptr[node], end = g_rowptr[node + 1];
        int i = beg;
        for (; i + 4 <= end; i += 4) {
            int s0 = g_csr[i], s1 = g_csr[i + 1], s2 = g_csr[i + 2], s3 = g_csr[i + 3];
            float n0 = dd * g_dis[s0], n1 = dd * g_dis[s1];
            float n2 = dd * g_dis[s2], n3 = dd * g_dis[s3];
            float4 v0 = *(const float4*)(xw + (long long)s0 * 64 + ch);
            float4 v1 = *(const float4*)(xw + (long long)s1 * 64 + ch);
            float4 v2 = *(const float4*)(xw + (long long)s2 * 64 + ch);
            float4 v3 = *(const float4*)(xw + (long long)s3 * 64 + ch);
            acc.x += n0 * v0.x + n1 * v1.x + n2 * v2.x + n3 * v3.x;
            acc.y += n0 * v0.y + n1 * v1.y + n2 * v2.y + n3 * v3.y;
            acc.z += n0 * v0.z + n1 * v1.z + n2 * v2.z + n3 * v3.z;
            acc.w += n0 * v0.w + n1 * v1.w + n2 * v2.w + n3 * v3.w;
        }
        for (; i < end; i++) {
            int s = g_csr[i];
            float nn = dd * g_dis[s];
            float4 v = *(const float4*)(xw + (long long)s * 64 + ch);
            acc.x += nn * v.x; acc.y += nn * v.y;
            acc.z += nn * v.z; acc.w += nn * v.w;
        }
        acc.x = fmaxf(acc.x, 0.f); acc.y = fmaxf(acc.y, 0.f);
        acc.z = fmaxf(acc.z, 0.f); acc.w = fmaxf(acc.w, 0.f);
        *(float4*)(out + node * 64 + ch) = acc;
        atomicAdd(&ss[ch + 0], acc.x); atomicAdd(&sq[ch + 0], acc.x * acc.x);
        atomicAdd(&ss[ch + 1], acc.y); atomicAdd(&sq[ch + 1], acc.y * acc.y);
        atomicAdd(&ss[ch + 2], acc.z); atomicAdd(&sq[ch + 2], acc.z * acc.z);
        atomicAdd(&ss[ch + 3], acc.w); atomicAdd(&sq[ch + 3], acc.w * acc.w);
    }
    __syncthreads();
    if (t < HC) { atomicAdd(&gsum[t], ss[t]); atomicAdd(&gsq[t], sq[t]); }
}

// ---------------- BN apply (in place) ----------------------------------------
__global__ void k_bn(float* __restrict__ buf, const float* __restrict__ gsum,
                     const float* __restrict__ gsq, const float* __restrict__ gamma,
                     const float* __restrict__ beta, float invN, long long n64) {
    long long idx = blockIdx.x * (long long)blockDim.x + threadIdx.x;
    if (idx >= n64) return;
    int c = (int)(idx & 63);
    float m   = gsum[c] * invN;
    float var = gsq[c] * invN - m * m;
    float sc  = rsqrtf(var + EPSV) * gamma[c];
    buf[idx] = (buf[idx] - m) * sc + beta[c];
}

// ---------------- BN apply + global mean pool accumulation ------------------
__global__ void k_bnpool(const float* __restrict__ buf, const float* __restrict__ gsum,
                         const float* __restrict__ gsq, const float* __restrict__ gamma,
                         const float* __restrict__ beta, const void* batch,
                         float invN, long long n64) {
    long long idx = blockIdx.x * (long long)blockDim.x + threadIdx.x;
    if (idx >= n64) return;
    long long i = idx >> 6;
    int c = (int)(idx & 63);
    float m   = gsum[c] * invN;
    float var = gsq[c] * invN - m * m;
    float sc  = rsqrtf(var + EPSV) * gamma[c];
    float val = (buf[idx] - m) * sc + beta[c];
    long long b = ld_idx(batch, i);
    atomicAdd(&g_pool[b * 64 + c], val);
    if (c == 0) atomicAdd(&g_cnt[b], 1.0f);
}

// ---------------- fused MLP head: one block per graph ------------------------
__global__ void k_mlp(const float* __restrict__ fw1, const float* __restrict__ fb1,
                      const float* __restrict__ fw2, const float* __restrict__ fb2,
                      const float* __restrict__ fw3, const float* __restrict__ fb3,
                      const float* __restrict__ fw4, const float* __restrict__ fb4,
                      const float* __restrict__ ow,  const float* __restrict__ ob,
                      float* __restrict__ out) {
    __shared__ float p[64], a1[128], a2[64], a3[32], a4[16];
    int g = blockIdx.x, t = threadIdx.x;
    float inv = 1.0f / fmaxf(g_cnt[g], 1.0f);
    if (t < 64) p[t] = g_pool[g * 64 + t] * inv;
    __syncthreads();
    if (t < 128) {
        float a = fb1[t];
#pragma unroll 8
        for (int k = 0; k < 64; k++) a += p[k] * fw1[k * 128 + t];
        a1[t] = fmaxf(a, 0.f);
    }
    __syncthreads();
    if (t < 64) {
        float a = fb2[t];
#pragma unroll 8
        for (int k = 0; k < 128; k++) a += a1[k] * fw2[k * 64 + t];
        a2[t] = fmaxf(a, 0.f);
    }
    __syncthreads();
    if (t < 32) {
        float a = fb3[t];
#pragma unroll 8
        for (int k = 0; k < 64; k++) a += a2[k] * fw3[k * 32 + t];
        a3[t] = fmaxf(a, 0.f);
    }
    __syncthreads();
    if (t < 16) {
        float a = fb4[t];
#pragma unroll
        for (int k = 0; k < 32; k++) a += a3[k] * fw4[k * 16 + t];
        a4[t] = fmaxf(a, 0.f);
    }
    __syncthreads();
    if (t < 2) {
        float a = ob[t];
#pragma unroll
        for (int k = 0; k < 16; k++) a += a4[k] * ow[k * 2 + t];
        out[g * 2 + t] = a;
    }
}

// ---------------- launcher ----------------------------------------------------
extern "C" void kernel_launch(void* const* d_in, const int* in_sizes, int n_in,
                              void* d_out, int out_size) {
    const float* x   = (const float*)d_in[0];
    const void*  ei  = d_in[1];
    const void*  bat = d_in[2];
    const float* w1  = (const float*)d_in[3];
    const float* b1  = (const float*)d_in[4];
    const float* w2  = (const float*)d_in[5];
    const float* b2  = (const float*)d_in[6];
    const float* g1  = (const float*)d_in[7];
    const float* be1 = (const float*)d_in[8];
    const float* g2  = (const float*)d_in[9];
    const float* be2 = (const float*)d_in[10];
    const float* fw1 = (const float*)d_in[11];
    const float* fb1 = (const float*)d_in[12];
    const float* fw2 = (const float*)d_in[13];
    const float* fb2 = (const float*)d_in[14];
    const float* fw3 = (const float*)d_in[15];
    const float* fb3 = (const float*)d_in[16];
    const float* fw4 = (const float*)d_in[17];
    const float* fb4 = (const float*)d_in[18];
    const float* ow  = (const float*)d_in[19];
    const float* ob  = (const float*)d_in[20];
    float* out = (float*)d_out;

    const long long N   = in_sizes[0] / 256;   // C = 256
    const long long E   = in_sizes[1] / 2;
    const int       G   = out_size / 2;
    const long long n64 = N * 64;
    const float invN = 1.0f / (float)N;

    float *bufA, *bufB, *sum1, *sq1, *sum2, *sq2;
    cudaGetSymbolAddress((void**)&bufA, g_bufA);
    cudaGetSymbolAddress((void**)&bufB, g_bufB);
    cudaGetSymbolAddress((void**)&sum1, g_sum1);
    cudaGetSymbolAddress((void**)&sq1,  g_sq1);
    cudaGetSymbolAddress((void**)&sum2, g_sum2);
    cudaGetSymbolAddress((void**)&sq2,  g_sq2);

    const int TB = 256;
    const int gN    = (int)((N + TB - 1) / TB);
    const int gE    = (int)((E + TB - 1) / TB);
    const int gN64  = (int)((n64 + TB - 1) / TB);
    const int gGemm = (int)((N + 31) / 32);
    const int gGath = (int)((N + 15) / 16);
    const int nb    = (int)((N + 255) / 256);

    // ---- index dtype + CSR build ----
    k_detect<<<1, 1>>>(ei, N);
    k_zero<<<gN, TB>>>(N);
    k_hist<<<gE, TB>>>(ei, E);
    k_scan1<<<nb, 256>>>(N);
    k_scan2<<<1, 512>>>(nb);
    k_scan3<<<gN, TB>>>(N, (int)E);
    k_scatter<<<gE, TB>>>(ei, E);

    // ---- GCN layer 1 ----
    k_gemm<256><<<gGemm, 128>>>(x, w1, bufA, N);
    k_gather<<<gGath, 256>>>(bufA, b1, bufB, N, sum1, sq1);
    k_bn<<<gN64, TB>>>(bufB, sum1, sq1, g1, be1, invN, n64);

    // ---- GCN layer 2 ----
    k_gemm<64><<<gGemm, 128>>>(bufB, w2, bufA, N);
    k_gather<<<gGath, 256>>>(bufA, b2, bufB, N, sum2, sq2);
    k_bnpool<<<gN64, TB>>>(bufB, sum2, sq2, g2, be2, bat, invN, n64);

    // ---- MLP head ----
    k_mlp<<<G, 128>>>(fw1, fb1, fw2, fb2, fw3, fb3, fw4, fb4, ow, ob, out);
}